// round 6
// baseline (speedup 1.0000x reference)
#include <cuda_runtime.h>
#include <math.h>
#include <stdint.h>

#define TOK    1568
#define BATCH  4
#define CDIM   768
#define TTOK   (BATCH*TOK)
#define QKVDIM 2304
#define HID    3072
#define NHEAD  12
#define DHEAD  64

__device__ float g_t[TTOK * CDIM];
__device__ float g_h[TTOK * CDIM];
__device__ float g_qkv[TTOK * QKVDIM];
__device__ float g_o[TTOK * CDIM];
__device__ float g_mlp[TTOK * HID];

// ---------------- ptx helpers ----------------
__device__ __forceinline__ void mma_tf32(float* d, const uint32_t* a, const uint32_t* b) {
    asm volatile(
        "mma.sync.aligned.m16n8k8.row.col.f32.tf32.tf32.f32 "
        "{%0,%1,%2,%3}, {%4,%5,%6,%7}, {%8,%9}, {%0,%1,%2,%3};"
        : "+f"(d[0]), "+f"(d[1]), "+f"(d[2]), "+f"(d[3])
        : "r"(a[0]), "r"(a[1]), "r"(a[2]), "r"(a[3]), "r"(b[0]), "r"(b[1]));
}
__device__ __forceinline__ void cp16(uint32_t dst, const void* src) {
    asm volatile("cp.async.cg.shared.global [%0], [%1], 16;" :: "r"(dst), "l"(src));
}
__device__ __forceinline__ void cp_commit() { asm volatile("cp.async.commit_group;"); }
template <int N> __device__ __forceinline__ void cp_wait() {
    asm volatile("cp.async.wait_group %0;" :: "n"(N));
}
__device__ __forceinline__ float gelu_exact(float v) {
    return 0.5f * v * (1.f + erff(v * 0.70710678118654752f));
}

// ---------------- conv + bias + residual + tokenize ----------------
__global__ void conv_pos_kernel(const float* __restrict__ x,
                                const float* __restrict__ pw,
                                const float* __restrict__ pb) {
    int bc = blockIdx.x;
    int c  = bc % CDIM;
    int b  = bc / CDIM;
    __shared__ float sx[TOK];
    __shared__ float sw[27];
    int tid = threadIdx.x;
    const float* xs = x + (size_t)bc * TOK;
    for (int i = tid; i < TOK; i += 256) sx[i] = xs[i];
    if (tid < 27) sw[tid] = pw[c * 27 + tid];
    __syncthreads();
    float pbv = pb[c];
    for (int idx = tid; idx < TOK; idx += 256) {
        int d = idx / 196; int r = idx - d * 196;
        int h = r / 14;    int w = r - h * 14;
        float acc = 0.f;
        #pragma unroll
        for (int kd = 0; kd < 3; kd++) {
            int dd = d + kd - 1;
            if (dd < 0 || dd >= 8) continue;
            #pragma unroll
            for (int kh = 0; kh < 3; kh++) {
                int hh = h + kh - 1;
                if (hh < 0 || hh >= 14) continue;
                #pragma unroll
                for (int kw = 0; kw < 3; kw++) {
                    int ww = w + kw - 1;
                    if (ww < 0 || ww >= 14) continue;
                    acc += sw[kd * 9 + kh * 3 + kw] * sx[dd * 196 + hh * 14 + ww];
                }
            }
        }
        g_t[(size_t)(b * TOK + idx) * CDIM + c] = sx[idx] + acc + pbv;
    }
}

// ---------------- LayerNorm ----------------
__global__ void ln_kernel(const float* __restrict__ in, const float* __restrict__ w,
                          const float* __restrict__ bsrc, float* __restrict__ out) {
    int t = blockIdx.x;
    int tid = threadIdx.x;
    const float* row = in + (size_t)t * CDIM;
    float v0 = row[tid], v1 = row[tid + 256], v2 = row[tid + 512];
    float s  = v0 + v1 + v2;
    float sq = v0 * v0 + v1 * v1 + v2 * v2;
    #pragma unroll
    for (int off = 16; off; off >>= 1) {
        s  += __shfl_xor_sync(0xffffffffu, s,  off);
        sq += __shfl_xor_sync(0xffffffffu, sq, off);
    }
    __shared__ float ss[8], ssq[8];
    int wid = tid >> 5, lid = tid & 31;
    if (lid == 0) { ss[wid] = s; ssq[wid] = sq; }
    __syncthreads();
    if (tid < 32) {
        s  = (lid < 8) ? ss[lid]  : 0.f;
        sq = (lid < 8) ? ssq[lid] : 0.f;
        #pragma unroll
        for (int off = 4; off; off >>= 1) {
            s  += __shfl_xor_sync(0xffffffffu, s,  off);
            sq += __shfl_xor_sync(0xffffffffu, sq, off);
        }
        if (lid == 0) { ss[0] = s; ssq[0] = sq; }
    }
    __syncthreads();
    float mean = ss[0] * (1.f / CDIM);
    float var  = ssq[0] * (1.f / CDIM) - mean * mean;
    float rs   = rsqrtf(var + 1e-5f);
    float* orow = out + (size_t)t * CDIM;
    orow[tid]       = (v0 - mean) * rs * w[tid]       + bsrc[tid];
    orow[tid + 256] = (v1 - mean) * rs * w[tid + 256] + bsrc[tid + 256];
    orow[tid + 512] = (v2 - mean) * rs * w[tid + 512] + bsrc[tid + 512];
}

// ---------------- tf32 mma.sync GEMM, BK=32, 2-stage cp.async, 1 barrier/chunk ----------------
// C[M,N] = A[M,K] @ B[N,K]^T. Block 128x128, 256 thr (8 warps), warp tile 64x32.
// Smem row-major stride 36 floats: fragment LDS banks (4*r0 + kq) distinct per warp.
#define GS_STRIDE 36
#define GS_MAT    (128 * GS_STRIDE)
#define GS_STAGE  (2 * GS_MAT)
#define GSMEM_B   (2 * GS_STAGE * 4)   // 73728 bytes

template <int MODE>
__global__ void __launch_bounds__(256, 2)
gemm_tc(const float* __restrict__ A, const float* __restrict__ B,
        const float* __restrict__ bias, const float* __restrict__ resid,
        float* __restrict__ C, int N, int K) {
    extern __shared__ __align__(16) float sm[];
    int tid = threadIdx.x;
    int lane = tid & 31, warp = tid >> 5;
    int wm = warp >> 2, wn = warp & 3;
    int m0 = blockIdx.y << 7, n0 = blockIdx.x << 7;

    // loader: thread -> rows (tid>>3) + {0,32,64,96}, col granule tid&7 (4 floats)
    int lrow = tid >> 3;
    int lc4  = (tid & 7) * 4;
    const float* Ag = A + (size_t)(m0 + lrow) * K + lc4;
    const float* Bg = B + (size_t)(n0 + lrow) * K + lc4;
    uint32_t sA = (uint32_t)__cvta_generic_to_shared(sm) + (lrow * GS_STRIDE + lc4) * 4;
    uint32_t sB = sA + GS_MAT * 4;
    const uint32_t ROWSTEP = 32 * GS_STRIDE * 4;
    const uint32_t STAGE_B = GS_STAGE * 4;

    int nch = K >> 5;
    auto load_chunk = [&](int ch) {
        uint32_t d = (ch & 1) ? STAGE_B : 0;
        int koff = ch << 5;
        #pragma unroll
        for (int i = 0; i < 4; i++) {
            cp16(sA + d + i * ROWSTEP, Ag + koff + (size_t)i * 32 * K);
            cp16(sB + d + i * ROWSTEP, Bg + koff + (size_t)i * 32 * K);
        }
        cp_commit();
    };

    float acc[4][4][4];
    #pragma unroll
    for (int mi = 0; mi < 4; mi++)
        #pragma unroll
        for (int ni = 0; ni < 4; ni++)
            #pragma unroll
            for (int r = 0; r < 4; r++) acc[mi][ni][r] = 0.f;

    int mbase = wm * 64 + (lane >> 2);
    int nbase = wn * 32 + (lane >> 2);
    int kq = lane & 3;

    load_chunk(0);
    for (int ch = 0; ch < nch; ch++) {
        cp_wait<0>();
        __syncthreads();
        if (ch + 1 < nch) load_chunk(ch + 1);
        const float* as = sm + (ch & 1) * GS_STAGE;
        const float* bs = as + GS_MAT;
        #pragma unroll
        for (int kb = 0; kb < 32; kb += 8) {
            int kk = kb + kq;
            uint32_t af[4][4], bf[4][2];
            #pragma unroll
            for (int mi = 0; mi < 4; mi++) {
                int m = mbase + mi * 16;
                af[mi][0] = __float_as_uint(as[m * GS_STRIDE + kk]);
                af[mi][1] = __float_as_uint(as[(m + 8) * GS_STRIDE + kk]);
                af[mi][2] = __float_as_uint(as[m * GS_STRIDE + kk + 4]);
                af[mi][3] = __float_as_uint(as[(m + 8) * GS_STRIDE + kk + 4]);
            }
            #pragma unroll
            for (int ni = 0; ni < 4; ni++) {
                int n = nbase + ni * 8;
                bf[ni][0] = __float_as_uint(bs[n * GS_STRIDE + kk]);
                bf[ni][1] = __float_as_uint(bs[n * GS_STRIDE + kk + 4]);
            }
            #pragma unroll
            for (int mi = 0; mi < 4; mi++)
                #pragma unroll
                for (int ni = 0; ni < 4; ni++)
                    mma_tf32(acc[mi][ni], af[mi], bf[ni]);
        }
    }

    // epilogue
    int r0 = lane >> 2, cq = (lane & 3) * 2;
    #pragma unroll
    for (int mi = 0; mi < 4; mi++) {
        int rowA = m0 + wm * 64 + mi * 16 + r0;
        int rowB = rowA + 8;
        #pragma unroll
        for (int ni = 0; ni < 4; ni++) {
            int col = n0 + wn * 32 + ni * 8 + cq;
            float2 va = make_float2(acc[mi][ni][0], acc[mi][ni][1]);
            float2 vb = make_float2(acc[mi][ni][2], acc[mi][ni][3]);
            if (MODE == 1) {
                float2 bv = *(const float2*)(bias + col);
                float2 ra = *(const float2*)(resid + (size_t)rowA * N + col);
                float2 rb = *(const float2*)(resid + (size_t)rowB * N + col);
                va.x += bv.x + ra.x; va.y += bv.y + ra.y;
                vb.x += bv.x + rb.x; vb.y += bv.y + rb.y;
            } else if (MODE == 2) {
                float2 bv = *(const float2*)(bias + col);
                va.x = gelu_exact(va.x + bv.x); va.y = gelu_exact(va.y + bv.y);
                vb.x = gelu_exact(vb.x + bv.x); vb.y = gelu_exact(vb.y + bv.y);
            }
            *(float2*)(C + (size_t)rowA * N + col) = va;
            *(float2*)(C + (size_t)rowB * N + col) = vb;
        }
    }
}

// ---------------- tf32 flash attention, cp.async pipelined ----------------
// 128 thr (4 warps), 64-query blocks. K double-buffered, V single, P separate.
// Per chunk: 2 barriers. V(ch) load overlaps S; K(ch+1) load overlaps PV.
#define AK_STRIDE 68
#define AV_STRIDE 72
#define A_KOFF(s) ((s) * 64 * AK_STRIDE)
#define A_VOFF    (2 * 64 * AK_STRIDE)
#define A_POFF    (A_VOFF + 64 * AV_STRIDE)
#define ASMEM_B   ((A_POFF + 64 * AK_STRIDE) * 4)   // 70656 bytes

__global__ void __launch_bounds__(128)
attn_tc(const float* __restrict__ qkv, float* __restrict__ o) {
    extern __shared__ __align__(16) float asm_f[];
    uint32_t smb = (uint32_t)__cvta_generic_to_shared(asm_f);
    int tid = threadIdx.x, lane = tid & 31, warp = tid >> 5;
    int bh = blockIdx.y;
    int b = bh / NHEAD, h = bh % NHEAD;
    int q0 = blockIdx.x * 64;
    const float* base = qkv + (size_t)b * TOK * QKVDIM + h * DHEAD;

    int r0 = lane >> 2, kq = lane & 3;
    uint32_t qf[8][4];
    {
        int qa = q0 + warp * 16 + r0;
        int qb = qa + 8;
        const float* pa = base + (size_t)qa * QKVDIM;
        const float* pb = base + (size_t)qb * QKVDIM;
        bool va = qa < TOK, vb = qb < TOK;
        #pragma unroll
        for (int kt = 0; kt < 8; kt++) {
            int k = kt * 8 + kq;
            qf[kt][0] = va ? __float_as_uint(pa[k] * 0.125f) : 0u;
            qf[kt][1] = vb ? __float_as_uint(pb[k] * 0.125f) : 0u;
            qf[kt][2] = va ? __float_as_uint(pa[k + 4] * 0.125f) : 0u;
            qf[kt][3] = vb ? __float_as_uint(pb[k + 4] * 0.125f) : 0u;
        }
    }

    // loader mapping: 8 granules per thread; row = g>>4, col = (g&15)*4
    int grow = tid >> 4;               // base row, step 8
    int gc4  = (tid & 15) * 4;
    auto loadK = [&](int kc, int st) {
        const float* src = base + CDIM + gc4;
        uint32_t dst = smb + (A_KOFF(st) + grow * AK_STRIDE + gc4) * 4;
        #pragma unroll
        for (int i = 0; i < 8; i++) {
            int kg = kc * 64 + grow + i * 8;
            if (kg > TOK - 1) kg = TOK - 1;
            cp16(dst + i * 8 * AK_STRIDE * 4, src + (size_t)kg * QKVDIM);
        }
        cp_commit();
    };
    auto loadV = [&](int kc) {
        const float* src = base + 2 * CDIM + gc4;
        uint32_t dst = smb + (A_VOFF + grow * AV_STRIDE + gc4) * 4;
        #pragma unroll
        for (int i = 0; i < 8; i++) {
            int kg = kc * 64 + grow + i * 8;
            if (kg > TOK - 1) kg = TOK - 1;
            cp16(dst + i * 8 * AV_STRIDE * 4, src + (size_t)kg * QKVDIM);
        }
        cp_commit();
    };

    float oacc[8][4];
    #pragma unroll
    for (int nt = 0; nt < 8; nt++)
        #pragma unroll
        for (int rr = 0; rr < 4; rr++) oacc[nt][rr] = 0.f;
    float mi0 = -1e30f, mi1 = -1e30f, li0 = 0.f, li1 = 0.f;

    loadK(0, 0);
    for (int kc = 0; kc < 25; kc++) {
        cp_wait<0>();        // K(kc) ready (V already drained at prev wait)
        __syncthreads();
        loadV(kc);           // overlaps S + softmax

        const float* Ks = asm_f + A_KOFF(kc & 1);
        float s[8][4];
        #pragma unroll
        for (int ni = 0; ni < 8; ni++)
            #pragma unroll
            for (int rr = 0; rr < 4; rr++) s[ni][rr] = 0.f;
        #pragma unroll
        for (int kt = 0; kt < 8; kt++) {
            int kk = kt * 8 + kq;
            #pragma unroll
            for (int ni = 0; ni < 8; ni++) {
                int n = ni * 8 + r0;
                uint32_t bf[2];
                bf[0] = __float_as_uint(Ks[n * AK_STRIDE + kk]);
                bf[1] = __float_as_uint(Ks[n * AK_STRIDE + kk + 4]);
                mma_tf32(s[ni], qf[kt], bf);
            }
        }
        if (kc == 24) {
            #pragma unroll
            for (int ni = 0; ni < 8; ni++) {
                int c = kc * 64 + ni * 8 + kq * 2;
                if (c >= TOK)     { s[ni][0] = -1e30f; s[ni][2] = -1e30f; }
                if (c + 1 >= TOK) { s[ni][1] = -1e30f; s[ni][3] = -1e30f; }
            }
        }
        float mr0 = -1e30f, mr1 = -1e30f;
        #pragma unroll
        for (int ni = 0; ni < 8; ni++) {
            mr0 = fmaxf(mr0, fmaxf(s[ni][0], s[ni][1]));
            mr1 = fmaxf(mr1, fmaxf(s[ni][2], s[ni][3]));
        }
        mr0 = fmaxf(mr0, __shfl_xor_sync(0xffffffffu, mr0, 1));
        mr0 = fmaxf(mr0, __shfl_xor_sync(0xffffffffu, mr0, 2));
        mr1 = fmaxf(mr1, __shfl_xor_sync(0xffffffffu, mr1, 1));
        mr1 = fmaxf(mr1, __shfl_xor_sync(0xffffffffu, mr1, 2));
        float mn0 = fmaxf(mi0, mr0), mn1 = fmaxf(mi1, mr1);
        float a0 = __expf(mi0 - mn0), a1 = __expf(mi1 - mn1);
        float sum0 = 0.f, sum1 = 0.f;
        #pragma unroll
        for (int ni = 0; ni < 8; ni++) {
            s[ni][0] = __expf(s[ni][0] - mn0);
            s[ni][1] = __expf(s[ni][1] - mn0);
            s[ni][2] = __expf(s[ni][2] - mn1);
            s[ni][3] = __expf(s[ni][3] - mn1);
            sum0 += s[ni][0] + s[ni][1];
            sum1 += s[ni][2] + s[ni][3];
        }
        sum0 += __shfl_xor_sync(0xffffffffu, sum0, 1);
        sum0 += __shfl_xor_sync(0xffffffffu, sum0, 2);
        sum1 += __shfl_xor_sync(0xffffffffu, sum1, 1);
        sum1 += __shfl_xor_sync(0xffffffffu, sum1, 2);
        li0 = li0 * a0 + sum0; li1 = li1 * a1 + sum1;
        mi0 = mn0; mi1 = mn1;
        #pragma unroll
        for (int nt = 0; nt < 8; nt++) {
            oacc[nt][0] *= a0; oacc[nt][1] *= a0;
            oacc[nt][2] *= a1; oacc[nt][3] *= a1;
        }

        if (kc + 1 < 25) loadK(kc + 1, (kc + 1) & 1);   // overlaps P-write + PV

        // write P (own warp rows only)
        float* Ps = asm_f + A_POFF;
        {
            int prow = warp * 16 + r0;
            #pragma unroll
            for (int ni = 0; ni < 8; ni++) {
                int col = ni * 8 + kq * 2;
                *(float2*)&Ps[prow * AK_STRIDE + col]       = make_float2(s[ni][0], s[ni][1]);
                *(float2*)&Ps[(prow + 8) * AK_STRIDE + col] = make_float2(s[ni][2], s[ni][3]);
            }
        }
        if (kc + 1 < 25) cp_wait<1>(); else cp_wait<0>();   // V(kc) done (K may stay pending)
        __syncthreads();

        const float* Vsm = asm_f + A_VOFF;
        #pragma unroll
        for (int kt = 0; kt < 8; kt++) {
            int kk = kt * 8 + kq;
            uint32_t pf[4];
            int prow = warp * 16 + r0;
            pf[0] = __float_as_uint(Ps[prow * AK_STRIDE + kk]);
            pf[1] = __float_as_uint(Ps[(prow + 8) * AK_STRIDE + kk]);
            pf[2] = __float_as_uint(Ps[prow * AK_STRIDE + kk + 4]);
            pf[3] = __float_as_uint(Ps[(prow + 8) * AK_STRIDE + kk + 4]);
            #pragma unroll
            for (int nt = 0; nt < 8; nt++) {
                int n = nt * 8 + r0;
                uint32_t bf[2];
                bf[0] = __float_as_uint(Vsm[kk * AV_STRIDE + n]);
                bf[1] = __float_as_uint(Vsm[(kk + 4) * AV_STRIDE + n]);
                mma_tf32(oacc[nt], pf, bf);
            }
        }
        __syncthreads();   // all PV reads of V done before next iter's loadV overwrite
    }

    int qa = q0 + warp * 16 + r0;
    int qb = qa + 8;
    float inv0 = 1.f / li0, inv1 = 1.f / li1;
    #pragma unroll
    for (int nt = 0; nt < 8; nt++) {
        int col = h * DHEAD + nt * 8 + kq * 2;
        if (qa < TOK)
            *(float2*)(o + (size_t)(b * TOK + qa) * CDIM + col) =
                make_float2(oacc[nt][0] * inv0, oacc[nt][1] * inv0);
        if (qb < TOK)
            *(float2*)(o + (size_t)(b * TOK + qb) * CDIM + col) =
                make_float2(oacc[nt][2] * inv1, oacc[nt][3] * inv1);
    }
}

// ---------------- untokenize ----------------
__global__ void untok_kernel(float* __restrict__ out) {
    __shared__ float tile[32][33];
    int b  = blockIdx.z;
    int s0 = blockIdx.x * 32;
    int c0 = blockIdx.y * 32;
    int tx = threadIdx.x, ty = threadIdx.y;
    #pragma unroll
    for (int r = ty; r < 32; r += 8)
        tile[r][tx] = g_t[(size_t)(b * TOK + s0 + r) * CDIM + c0 + tx];
    __syncthreads();
    #pragma unroll
    for (int r = ty; r < 32; r += 8)
        out[(size_t)(b * CDIM + c0 + r) * TOK + s0 + tx] = tile[tx][r];
}

// ---------------- launch ----------------
extern "C" void kernel_launch(void* const* d_in, const int* in_sizes, int n_in,
                              void* d_out, int out_size) {
    const float* x      = (const float*)d_in[0];
    const float* pos_w  = (const float*)d_in[1];
    const float* pos_b  = (const float*)d_in[2];
    const float* ln1_w  = (const float*)d_in[3];
    const float* ln1_b  = (const float*)d_in[4];
    const float* qkv_w  = (const float*)d_in[5];
    const float* proj_w = (const float*)d_in[6];
    const float* proj_b = (const float*)d_in[7];
    const float* ln2_w  = (const float*)d_in[8];
    const float* ln2_b  = (const float*)d_in[9];
    const float* fc1_w  = (const float*)d_in[10];
    const float* fc1_b  = (const float*)d_in[11];
    const float* fc2_w  = (const float*)d_in[12];
    const float* fc2_b  = (const float*)d_in[13];
    float* out = (float*)d_out;

    float *t, *hbuf, *qkvb, *ob, *mlpb;
    cudaGetSymbolAddress((void**)&t,    g_t);
    cudaGetSymbolAddress((void**)&hbuf, g_h);
    cudaGetSymbolAddress((void**)&qkvb, g_qkv);
    cudaGetSymbolAddress((void**)&ob,   g_o);
    cudaGetSymbolAddress((void**)&mlpb, g_mlp);

    cudaFuncSetAttribute(gemm_tc<0>, cudaFuncAttributeMaxDynamicSharedMemorySize, GSMEM_B);
    cudaFuncSetAttribute(gemm_tc<1>, cudaFuncAttributeMaxDynamicSharedMemorySize, GSMEM_B);
    cudaFuncSetAttribute(gemm_tc<2>, cudaFuncAttributeMaxDynamicSharedMemorySize, GSMEM_B);
    cudaFuncSetAttribute(attn_tc,    cudaFuncAttributeMaxDynamicSharedMemorySize, ASMEM_B);

    conv_pos_kernel<<<BATCH * CDIM, 256>>>(x, pos_w, pos_b);
    ln_kernel<<<TTOK, 256>>>(t, ln1_w, ln1_b, hbuf);
    gemm_tc<0><<<dim3(QKVDIM / 128, TTOK / 128), 256, GSMEM_B>>>(hbuf, qkv_w, nullptr, nullptr,
                                                                 qkvb, QKVDIM, CDIM);
    attn_tc<<<dim3(25, BATCH * NHEAD), 128, ASMEM_B>>>(qkvb, ob);
    gemm_tc<1><<<dim3(CDIM / 128, TTOK / 128), 256, GSMEM_B>>>(ob, proj_w, proj_b, t,
                                                               t, CDIM, CDIM);
    ln_kernel<<<TTOK, 256>>>(t, ln2_w, ln2_b, hbuf);
    gemm_tc<2><<<dim3(HID / 128, TTOK / 128), 256, GSMEM_B>>>(hbuf, fc1_w, fc1_b, nullptr,
                                                              mlpb, HID, CDIM);
    gemm_tc<1><<<dim3(CDIM / 128, TTOK / 128), 256, GSMEM_B>>>(mlpb, fc2_w, fc2_b, t,
                                                               t, CDIM, HID);
    untok_kernel<<<dim3(TOK / 32, CDIM / 32, BATCH), dim3(32, 8)>>>(out);
}

// round 7
// speedup vs baseline: 1.2222x; 1.2222x over previous
#include <cuda_runtime.h>
#include <math.h>
#include <stdint.h>

#define TOK    1568
#define BATCH  4
#define CDIM   768
#define TTOK   (BATCH*TOK)
#define QKVDIM 2304
#define HID    3072
#define NHEAD  12
#define DHEAD  64

__device__ float g_t[TTOK * CDIM];
__device__ float g_h[TTOK * CDIM];
__device__ float g_qkv[TTOK * QKVDIM];
__device__ float g_o[TTOK * CDIM];
__device__ float g_mlp[TTOK * HID];

// ---------------- ptx helpers ----------------
__device__ __forceinline__ void mma_tf32(float* d, const uint32_t* a, const uint32_t* b) {
    asm volatile(
        "mma.sync.aligned.m16n8k8.row.col.f32.tf32.tf32.f32 "
        "{%0,%1,%2,%3}, {%4,%5,%6,%7}, {%8,%9}, {%0,%1,%2,%3};"
        : "+f"(d[0]), "+f"(d[1]), "+f"(d[2]), "+f"(d[3])
        : "r"(a[0]), "r"(a[1]), "r"(a[2]), "r"(a[3]), "r"(b[0]), "r"(b[1]));
}
__device__ __forceinline__ void cp16(uint32_t dst, const void* src) {
    asm volatile("cp.async.cg.shared.global [%0], [%1], 16;" :: "r"(dst), "l"(src));
}
__device__ __forceinline__ void cp_commit() { asm volatile("cp.async.commit_group;"); }
template <int N> __device__ __forceinline__ void cp_wait() {
    asm volatile("cp.async.wait_group %0;" :: "n"(N));
}
__device__ __forceinline__ float gelu_exact(float v) {
    return 0.5f * v * (1.f + erff(v * 0.70710678118654752f));
}

// ---------------- conv + bias + residual + tokenize ----------------
__global__ void conv_pos_kernel(const float* __restrict__ x,
                                const float* __restrict__ pw,
                                const float* __restrict__ pb) {
    int bc = blockIdx.x;
    int c  = bc % CDIM;
    int b  = bc / CDIM;
    __shared__ float sx[TOK];
    __shared__ float sw[27];
    int tid = threadIdx.x;
    const float* xs = x + (size_t)bc * TOK;
    for (int i = tid; i < TOK; i += 256) sx[i] = xs[i];
    if (tid < 27) sw[tid] = pw[c * 27 + tid];
    __syncthreads();
    float pbv = pb[c];
    for (int idx = tid; idx < TOK; idx += 256) {
        int d = idx / 196; int r = idx - d * 196;
        int h = r / 14;    int w = r - h * 14;
        float acc = 0.f;
        #pragma unroll
        for (int kd = 0; kd < 3; kd++) {
            int dd = d + kd - 1;
            if (dd < 0 || dd >= 8) continue;
            #pragma unroll
            for (int kh = 0; kh < 3; kh++) {
                int hh = h + kh - 1;
                if (hh < 0 || hh >= 14) continue;
                #pragma unroll
                for (int kw = 0; kw < 3; kw++) {
                    int ww = w + kw - 1;
                    if (ww < 0 || ww >= 14) continue;
                    acc += sw[kd * 9 + kh * 3 + kw] * sx[dd * 196 + hh * 14 + ww];
                }
            }
        }
        g_t[(size_t)(b * TOK + idx) * CDIM + c] = sx[idx] + acc + pbv;
    }
}

// ---------------- LayerNorm ----------------
__global__ void ln_kernel(const float* __restrict__ in, const float* __restrict__ w,
                          const float* __restrict__ bsrc, float* __restrict__ out) {
    int t = blockIdx.x;
    int tid = threadIdx.x;
    const float* row = in + (size_t)t * CDIM;
    float v0 = row[tid], v1 = row[tid + 256], v2 = row[tid + 512];
    float s  = v0 + v1 + v2;
    float sq = v0 * v0 + v1 * v1 + v2 * v2;
    #pragma unroll
    for (int off = 16; off; off >>= 1) {
        s  += __shfl_xor_sync(0xffffffffu, s,  off);
        sq += __shfl_xor_sync(0xffffffffu, sq, off);
    }
    __shared__ float ss[8], ssq[8];
    int wid = tid >> 5, lid = tid & 31;
    if (lid == 0) { ss[wid] = s; ssq[wid] = sq; }
    __syncthreads();
    if (tid < 32) {
        s  = (lid < 8) ? ss[lid]  : 0.f;
        sq = (lid < 8) ? ssq[lid] : 0.f;
        #pragma unroll
        for (int off = 4; off; off >>= 1) {
            s  += __shfl_xor_sync(0xffffffffu, s,  off);
            sq += __shfl_xor_sync(0xffffffffu, sq, off);
        }
        if (lid == 0) { ss[0] = s; ssq[0] = sq; }
    }
    __syncthreads();
    float mean = ss[0] * (1.f / CDIM);
    float var  = ssq[0] * (1.f / CDIM) - mean * mean;
    float rs   = rsqrtf(var + 1e-5f);
    float* orow = out + (size_t)t * CDIM;
    orow[tid]       = (v0 - mean) * rs * w[tid]       + bsrc[tid];
    orow[tid + 256] = (v1 - mean) * rs * w[tid + 256] + bsrc[tid + 256];
    orow[tid + 512] = (v2 - mean) * rs * w[tid + 512] + bsrc[tid + 512];
}

// ---------------- tf32 mma.sync GEMM: BK=16, 3-stage cp.async, 1 barrier/chunk ----------------
// C[M,N] = A[M,K] @ B[N,K]^T. Block 128x128, 256 thr (8 warps), warp tile 64x32.
// Row-major smem stride 20 floats. Stage = A(2560)+B(2560) floats = 20480 B; 3 stages.
#define G_STRIDE 20
#define G_MATF   (128 * G_STRIDE)          // 2560 floats
#define G_STAGEF (2 * G_MATF)              // 5120 floats
#define GSMEM_B  (3 * G_STAGEF * 4)        // 61440 bytes

template <int MODE>
__global__ void __launch_bounds__(256, 2)
gemm_tc(const float* __restrict__ A, const float* __restrict__ B,
        const float* __restrict__ bias, const float* __restrict__ resid,
        float* __restrict__ C, int N, int K) {
    extern __shared__ __align__(16) float sm[];
    int tid = threadIdx.x;
    int lane = tid & 31, warp = tid >> 5;
    int wm = warp >> 2, wn = warp & 3;
    int m0 = blockIdx.y << 7, n0 = blockIdx.x << 7;

    int lrow = tid >> 1;
    int lc   = (tid & 1) * 8;
    const float* Ag = A + (size_t)(m0 + lrow) * K + lc;
    const float* Bg = B + (size_t)(n0 + lrow) * K + lc;
    uint32_t sa0 = (uint32_t)__cvta_generic_to_shared(sm) + (lrow * G_STRIDE + lc) * 4;
    uint32_t sb0 = sa0 + G_MATF * 4;

    int nch = K >> 4;
    auto load_chunk = [&](int ch) {
        uint32_t d = (uint32_t)(ch % 3) * (G_STAGEF * 4);
        int off = ch << 4;
        cp16(sa0 + d, Ag + off); cp16(sa0 + d + 16, Ag + off + 4);
        cp16(sb0 + d, Bg + off); cp16(sb0 + d + 16, Bg + off + 4);
        cp_commit();
    };

    float acc[4][4][4];
    #pragma unroll
    for (int mi = 0; mi < 4; mi++)
        #pragma unroll
        for (int ni = 0; ni < 4; ni++)
            #pragma unroll
            for (int r = 0; r < 4; r++) acc[mi][ni][r] = 0.f;

    int mbase = wm * 64 + (lane >> 2);
    int nbase = wn * 32 + (lane >> 2);
    int kq = lane & 3;

    load_chunk(0);
    load_chunk(1);
    for (int ch = 0; ch < nch; ch++) {
        if (ch < nch - 1) cp_wait<1>(); else cp_wait<0>();
        __syncthreads();
        if (ch + 2 < nch) load_chunk(ch + 2);   // buffer (ch+2)%3 == (ch-1)%3, freed by barrier
        const float* as = sm + (ch % 3) * G_STAGEF;
        const float* bs = as + G_MATF;
        #pragma unroll
        for (int kb = 0; kb < 16; kb += 8) {
            int kk = kb + kq;
            uint32_t af[4][4], bf[4][2];
            #pragma unroll
            for (int mi = 0; mi < 4; mi++) {
                int m = mbase + mi * 16;
                af[mi][0] = __float_as_uint(as[m * G_STRIDE + kk]);
                af[mi][1] = __float_as_uint(as[(m + 8) * G_STRIDE + kk]);
                af[mi][2] = __float_as_uint(as[m * G_STRIDE + kk + 4]);
                af[mi][3] = __float_as_uint(as[(m + 8) * G_STRIDE + kk + 4]);
            }
            #pragma unroll
            for (int ni = 0; ni < 4; ni++) {
                int n = nbase + ni * 8;
                bf[ni][0] = __float_as_uint(bs[n * G_STRIDE + kk]);
                bf[ni][1] = __float_as_uint(bs[n * G_STRIDE + kk + 4]);
            }
            #pragma unroll
            for (int mi = 0; mi < 4; mi++)
                #pragma unroll
                for (int ni = 0; ni < 4; ni++)
                    mma_tf32(acc[mi][ni], af[mi], bf[ni]);
        }
    }

    // epilogue
    int r0 = lane >> 2, cq = (lane & 3) * 2;
    #pragma unroll
    for (int mi = 0; mi < 4; mi++) {
        int rowA = m0 + wm * 64 + mi * 16 + r0;
        int rowB = rowA + 8;
        #pragma unroll
        for (int ni = 0; ni < 4; ni++) {
            int col = n0 + wn * 32 + ni * 8 + cq;
            float2 va = make_float2(acc[mi][ni][0], acc[mi][ni][1]);
            float2 vb = make_float2(acc[mi][ni][2], acc[mi][ni][3]);
            if (MODE == 1) {
                float2 bv = *(const float2*)(bias + col);
                float2 ra = *(const float2*)(resid + (size_t)rowA * N + col);
                float2 rb = *(const float2*)(resid + (size_t)rowB * N + col);
                va.x += bv.x + ra.x; va.y += bv.y + ra.y;
                vb.x += bv.x + rb.x; vb.y += bv.y + rb.y;
            } else if (MODE == 2) {
                float2 bv = *(const float2*)(bias + col);
                va.x = gelu_exact(va.x + bv.x); va.y = gelu_exact(va.y + bv.y);
                vb.x = gelu_exact(vb.x + bv.x); vb.y = gelu_exact(vb.y + bv.y);
            }
            *(float2*)(C + (size_t)rowA * N + col) = va;
            *(float2*)(C + (size_t)rowB * N + col) = vb;
        }
    }
}

// ---------------- tf32 flash attention (exact R4 version, 4 CTAs/SM) ----------------
__global__ void __launch_bounds__(128)
attn_tc(const float* __restrict__ qkv, float* __restrict__ o) {
    __shared__ __align__(16) float KP[64 * 68];
    __shared__ __align__(16) float Vs[64 * 72];
    int tid = threadIdx.x, lane = tid & 31, warp = tid >> 5;
    int bh = blockIdx.y;
    int b = bh / NHEAD, h = bh % NHEAD;
    int q0 = blockIdx.x * 64;
    const float* base = qkv + (size_t)b * TOK * QKVDIM + h * DHEAD;

    int r0 = lane >> 2, kq = lane & 3;
    uint32_t qf[8][4];
    {
        int qa = q0 + warp * 16 + r0;
        int qb = qa + 8;
        const float* pa = base + (size_t)qa * QKVDIM;
        const float* pb = base + (size_t)qb * QKVDIM;
        bool va = qa < TOK, vb = qb < TOK;
        #pragma unroll
        for (int kt = 0; kt < 8; kt++) {
            int k = kt * 8 + kq;
            qf[kt][0] = va ? __float_as_uint(pa[k] * 0.125f) : 0u;
            qf[kt][1] = vb ? __float_as_uint(pb[k] * 0.125f) : 0u;
            qf[kt][2] = va ? __float_as_uint(pa[k + 4] * 0.125f) : 0u;
            qf[kt][3] = vb ? __float_as_uint(pb[k + 4] * 0.125f) : 0u;
        }
    }

    float oacc[8][4];
    #pragma unroll
    for (int nt = 0; nt < 8; nt++)
        #pragma unroll
        for (int rr = 0; rr < 4; rr++) oacc[nt][rr] = 0.f;
    float mi0 = -1e30f, mi1 = -1e30f, li0 = 0.f, li1 = 0.f;

    for (int kc = 0; kc < 25; kc++) {
        __syncthreads();
        #pragma unroll
        for (int i = 0; i < 8; i++) {
            int q = tid + i * 128;
            int key = q >> 4;
            int d4  = (q & 15) << 2;
            int kg = kc * 64 + key;
            float4 kv = make_float4(0.f, 0.f, 0.f, 0.f);
            float4 vv = make_float4(0.f, 0.f, 0.f, 0.f);
            if (kg < TOK) {
                kv = *(const float4*)(base + (size_t)kg * QKVDIM + CDIM + d4);
                vv = *(const float4*)(base + (size_t)kg * QKVDIM + 2 * CDIM + d4);
            }
            *(float4*)&KP[key * 68 + d4] = kv;
            *(float4*)&Vs[key * 72 + d4] = vv;
        }
        __syncthreads();

        float s[8][4];
        #pragma unroll
        for (int ni = 0; ni < 8; ni++)
            #pragma unroll
            for (int rr = 0; rr < 4; rr++) s[ni][rr] = 0.f;
        #pragma unroll
        for (int kt = 0; kt < 8; kt++) {
            int kk = kt * 8 + kq;
            #pragma unroll
            for (int ni = 0; ni < 8; ni++) {
                int n = ni * 8 + r0;
                uint32_t bf[2];
                bf[0] = __float_as_uint(KP[n * 68 + kk]);
                bf[1] = __float_as_uint(KP[n * 68 + kk + 4]);
                mma_tf32(s[ni], qf[kt], bf);
            }
        }
        if (kc == 24) {
            #pragma unroll
            for (int ni = 0; ni < 8; ni++) {
                int c = kc * 64 + ni * 8 + kq * 2;
                if (c >= TOK)     { s[ni][0] = -1e30f; s[ni][2] = -1e30f; }
                if (c + 1 >= TOK) { s[ni][1] = -1e30f; s[ni][3] = -1e30f; }
            }
        }
        float mr0 = -1e30f, mr1 = -1e30f;
        #pragma unroll
        for (int ni = 0; ni < 8; ni++) {
            mr0 = fmaxf(mr0, fmaxf(s[ni][0], s[ni][1]));
            mr1 = fmaxf(mr1, fmaxf(s[ni][2], s[ni][3]));
        }
        mr0 = fmaxf(mr0, __shfl_xor_sync(0xffffffffu, mr0, 1));
        mr0 = fmaxf(mr0, __shfl_xor_sync(0xffffffffu, mr0, 2));
        mr1 = fmaxf(mr1, __shfl_xor_sync(0xffffffffu, mr1, 1));
        mr1 = fmaxf(mr1, __shfl_xor_sync(0xffffffffu, mr1, 2));
        float mn0 = fmaxf(mi0, mr0), mn1 = fmaxf(mi1, mr1);
        float a0 = __expf(mi0 - mn0), a1 = __expf(mi1 - mn1);
        float sum0 = 0.f, sum1 = 0.f;
        #pragma unroll
        for (int ni = 0; ni < 8; ni++) {
            s[ni][0] = __expf(s[ni][0] - mn0);
            s[ni][1] = __expf(s[ni][1] - mn0);
            s[ni][2] = __expf(s[ni][2] - mn1);
            s[ni][3] = __expf(s[ni][3] - mn1);
            sum0 += s[ni][0] + s[ni][1];
            sum1 += s[ni][2] + s[ni][3];
        }
        sum0 += __shfl_xor_sync(0xffffffffu, sum0, 1);
        sum0 += __shfl_xor_sync(0xffffffffu, sum0, 2);
        sum1 += __shfl_xor_sync(0xffffffffu, sum1, 1);
        sum1 += __shfl_xor_sync(0xffffffffu, sum1, 2);
        li0 = li0 * a0 + sum0; li1 = li1 * a1 + sum1;
        mi0 = mn0; mi1 = mn1;
        #pragma unroll
        for (int nt = 0; nt < 8; nt++) {
            oacc[nt][0] *= a0; oacc[nt][1] *= a0;
            oacc[nt][2] *= a1; oacc[nt][3] *= a1;
        }
        __syncthreads();
        {
            int prow = warp * 16 + r0;
            #pragma unroll
            for (int ni = 0; ni < 8; ni++) {
                int col = ni * 8 + kq * 2;
                *(float2*)&KP[prow * 68 + col]       = make_float2(s[ni][0], s[ni][1]);
                *(float2*)&KP[(prow + 8) * 68 + col] = make_float2(s[ni][2], s[ni][3]);
            }
        }
        __syncwarp();
        #pragma unroll
        for (int kt = 0; kt < 8; kt++) {
            int kk = kt * 8 + kq;
            uint32_t pf[4];
            int prow = warp * 16 + r0;
            pf[0] = __float_as_uint(KP[prow * 68 + kk]);
            pf[1] = __float_as_uint(KP[(prow + 8) * 68 + kk]);
            pf[2] = __float_as_uint(KP[prow * 68 + kk + 4]);
            pf[3] = __float_as_uint(KP[(prow + 8) * 68 + kk + 4]);
            #pragma unroll
            for (int nt = 0; nt < 8; nt++) {
                int n = nt * 8 + r0;
                uint32_t bf[2];
                bf[0] = __float_as_uint(Vs[kk * 72 + n]);
                bf[1] = __float_as_uint(Vs[(kk + 4) * 72 + n]);
                mma_tf32(oacc[nt], pf, bf);
            }
        }
    }

    int qa = q0 + warp * 16 + r0;
    int qb = qa + 8;
    float inv0 = 1.f / li0, inv1 = 1.f / li1;
    #pragma unroll
    for (int nt = 0; nt < 8; nt++) {
        int col = h * DHEAD + nt * 8 + kq * 2;
        if (qa < TOK)
            *(float2*)(o + (size_t)(b * TOK + qa) * CDIM + col) =
                make_float2(oacc[nt][0] * inv0, oacc[nt][1] * inv0);
        if (qb < TOK)
            *(float2*)(o + (size_t)(b * TOK + qb) * CDIM + col) =
                make_float2(oacc[nt][2] * inv1, oacc[nt][3] * inv1);
    }
}

// ---------------- untokenize ----------------
__global__ void untok_kernel(float* __restrict__ out) {
    __shared__ float tile[32][33];
    int b  = blockIdx.z;
    int s0 = blockIdx.x * 32;
    int c0 = blockIdx.y * 32;
    int tx = threadIdx.x, ty = threadIdx.y;
    #pragma unroll
    for (int r = ty; r < 32; r += 8)
        tile[r][tx] = g_t[(size_t)(b * TOK + s0 + r) * CDIM + c0 + tx];
    __syncthreads();
    #pragma unroll
    for (int r = ty; r < 32; r += 8)
        out[(size_t)(b * CDIM + c0 + r) * TOK + s0 + tx] = tile[tx][r];
}

// ---------------- launch ----------------
extern "C" void kernel_launch(void* const* d_in, const int* in_sizes, int n_in,
                              void* d_out, int out_size) {
    const float* x      = (const float*)d_in[0];
    const float* pos_w  = (const float*)d_in[1];
    const float* pos_b  = (const float*)d_in[2];
    const float* ln1_w  = (const float*)d_in[3];
    const float* ln1_b  = (const float*)d_in[4];
    const float* qkv_w  = (const float*)d_in[5];
    const float* proj_w = (const float*)d_in[6];
    const float* proj_b = (const float*)d_in[7];
    const float* ln2_w  = (const float*)d_in[8];
    const float* ln2_b  = (const float*)d_in[9];
    const float* fc1_w  = (const float*)d_in[10];
    const float* fc1_b  = (const float*)d_in[11];
    const float* fc2_w  = (const float*)d_in[12];
    const float* fc2_b  = (const float*)d_in[13];
    float* out = (float*)d_out;

    float *t, *hbuf, *qkvb, *ob, *mlpb;
    cudaGetSymbolAddress((void**)&t,    g_t);
    cudaGetSymbolAddress((void**)&hbuf, g_h);
    cudaGetSymbolAddress((void**)&qkvb, g_qkv);
    cudaGetSymbolAddress((void**)&ob,   g_o);
    cudaGetSymbolAddress((void**)&mlpb, g_mlp);

    cudaFuncSetAttribute(gemm_tc<0>, cudaFuncAttributeMaxDynamicSharedMemorySize, GSMEM_B);
    cudaFuncSetAttribute(gemm_tc<1>, cudaFuncAttributeMaxDynamicSharedMemorySize, GSMEM_B);
    cudaFuncSetAttribute(gemm_tc<2>, cudaFuncAttributeMaxDynamicSharedMemorySize, GSMEM_B);

    conv_pos_kernel<<<BATCH * CDIM, 256>>>(x, pos_w, pos_b);
    ln_kernel<<<TTOK, 256>>>(t, ln1_w, ln1_b, hbuf);
    gemm_tc<0><<<dim3(QKVDIM / 128, TTOK / 128), 256, GSMEM_B>>>(hbuf, qkv_w, nullptr, nullptr,
                                                                 qkvb, QKVDIM, CDIM);
    attn_tc<<<dim3(25, BATCH * NHEAD), 128>>>(qkvb, ob);
    gemm_tc<1><<<dim3(CDIM / 128, TTOK / 128), 256, GSMEM_B>>>(ob, proj_w, proj_b, t,
                                                               t, CDIM, CDIM);
    ln_kernel<<<TTOK, 256>>>(t, ln2_w, ln2_b, hbuf);
    gemm_tc<2><<<dim3(HID / 128, TTOK / 128), 256, GSMEM_B>>>(hbuf, fc1_w, fc1_b, nullptr,
                                                              mlpb, HID, CDIM);
    gemm_tc<1><<<dim3(CDIM / 128, TTOK / 128), 256, GSMEM_B>>>(mlpb, fc2_w, fc2_b, t,
                                                               t, CDIM, HID);
    untok_kernel<<<dim3(TOK / 32, CDIM / 32, BATCH), dim3(32, 8)>>>(out);
}